// round 2
// baseline (speedup 1.0000x reference)
#include <cuda_runtime.h>
#include <cuda_bf16.h>

// Problem constants (fixed by the reference)
#define N_EDGES    8388608
#define N_QUADS    2097152     // N_EDGES / 4
#define NUM_GRAPHS 1024

#define MAIN_BLOCKS  2368      // 148 SMs * 16
#define MAIN_THREADS 256

__device__ float g_partials[4096];

// out = sum over edges of exp(-||pos[dst]-pos[src]||), computed as block partials.
// Edge index array is int32 [2, E] row-major: row 0 = src, row 1 = dst.
// 4 edges per iteration via int4 loads of each row.
__global__ void __launch_bounds__(MAIN_THREADS)
occl_main_kernel(const float2* __restrict__ pos,
                 const int4* __restrict__ src4,
                 const int4* __restrict__ dst4)
{
    int tid    = blockIdx.x * blockDim.x + threadIdx.x;
    int stride = gridDim.x * blockDim.x;

    float acc = 0.0f;

    for (int p = tid; p < N_QUADS; p += stride) {
        int4 s = __ldg(&src4[p]);
        int4 d = __ldg(&dst4[p]);

        float2 ps0 = __ldg(&pos[s.x]);
        float2 ps1 = __ldg(&pos[s.y]);
        float2 ps2 = __ldg(&pos[s.z]);
        float2 ps3 = __ldg(&pos[s.w]);
        float2 pd0 = __ldg(&pos[d.x]);
        float2 pd1 = __ldg(&pos[d.y]);
        float2 pd2 = __ldg(&pos[d.z]);
        float2 pd3 = __ldg(&pos[d.w]);

        float dx0 = pd0.x - ps0.x, dy0 = pd0.y - ps0.y;
        float dx1 = pd1.x - ps1.x, dy1 = pd1.y - ps1.y;
        float dx2 = pd2.x - ps2.x, dy2 = pd2.y - ps2.y;
        float dx3 = pd3.x - ps3.x, dy3 = pd3.y - ps3.y;

        float r0 = sqrtf(fmaf(dx0, dx0, dy0 * dy0));
        float r1 = sqrtf(fmaf(dx1, dx1, dy1 * dy1));
        float r2 = sqrtf(fmaf(dx2, dx2, dy2 * dy2));
        float r3 = sqrtf(fmaf(dx3, dx3, dy3 * dy3));

        acc += __expf(-r0) + __expf(-r1) + __expf(-r2) + __expf(-r3);
    }

    // warp reduce
    #pragma unroll
    for (int off = 16; off > 0; off >>= 1)
        acc += __shfl_xor_sync(0xFFFFFFFFu, acc, off);

    // block reduce via smem
    __shared__ float warp_sums[MAIN_THREADS / 32];
    int lane = threadIdx.x & 31;
    int wid  = threadIdx.x >> 5;
    if (lane == 0) warp_sums[wid] = acc;
    __syncthreads();

    if (wid == 0) {
        float b = (lane < (MAIN_THREADS / 32)) ? warp_sums[lane] : 0.0f;
        #pragma unroll
        for (int off = 16; off > 0; off >>= 1)
            b += __shfl_xor_sync(0xFFFFFFFFu, b, off);
        if (lane == 0) g_partials[blockIdx.x] = b;
    }
}

// Finalize: sum block partials, divide by NUM_GRAPHS, write scalar out.
__global__ void occl_final_kernel(float* __restrict__ out)
{
    __shared__ float warp_sums[8];
    float s = 0.0f;
    for (int i = threadIdx.x; i < MAIN_BLOCKS; i += 256)
        s += g_partials[i];

    #pragma unroll
    for (int off = 16; off > 0; off >>= 1)
        s += __shfl_xor_sync(0xFFFFFFFFu, s, off);

    int lane = threadIdx.x & 31;
    int wid  = threadIdx.x >> 5;
    if (lane == 0) warp_sums[wid] = s;
    __syncthreads();

    if (wid == 0) {
        float b = (lane < 8) ? warp_sums[lane] : 0.0f;
        #pragma unroll
        for (int off = 16; off > 0; off >>= 1)
            b += __shfl_xor_sync(0xFFFFFFFFu, b, off);
        if (lane == 0)
            out[0] = b * (1.0f / (float)NUM_GRAPHS);
    }
}

extern "C" void kernel_launch(void* const* d_in, const int* in_sizes, int n_in,
                              void* d_out, int out_size)
{
    // metadata order: node_pos f32 [131072,2], full_edge_index int32 [2, 8388608],
    //                 batch_idx int32 [131072] (unused: mean over full segment_sum
    //                 == total_sum / NUM_GRAPHS since all indices are in range)
    const float2* pos  = (const float2*)d_in[0];
    const int*    eidx = (const int*)d_in[1];
    float*        out  = (float*)d_out;

    const int4* src4 = (const int4*)(eidx);            // row 0
    const int4* dst4 = (const int4*)(eidx + N_EDGES);  // row 1

    occl_main_kernel<<<MAIN_BLOCKS, MAIN_THREADS>>>(pos, src4, dst4);
    occl_final_kernel<<<1, 256>>>(out);
}

// round 3
// speedup vs baseline: 1.5997x; 1.5997x over previous
#include <cuda_runtime.h>
#include <cuda_bf16.h>

// Problem constants (fixed by the reference)
#define N_EDGES    8388608
#define N_QUADS    2097152     // N_EDGES / 4
#define NUM_GRAPHS 1024

#define MAIN_BLOCKS  1184      // 148 SMs * 8 blocks -> exactly one wave @256thr
#define MAIN_THREADS 256

__device__ float        g_partials[MAIN_BLOCKS];
__device__ unsigned int g_count = 0;   // returns to 0 every launch (last block resets)

// out = (1/NUM_GRAPHS) * sum over edges of exp(-||pos[dst]-pos[src]||).
// Edge index array is int32 [2, E] row-major: row 0 = src, row 1 = dst.
// 4 edges per iteration via int4 loads of each row; unroll 2 for MLP.
__global__ void __launch_bounds__(MAIN_THREADS)
occl_kernel(const float2* __restrict__ pos,
            const int4* __restrict__ src4,
            const int4* __restrict__ dst4,
            float* __restrict__ out)
{
    const int tid    = blockIdx.x * blockDim.x + threadIdx.x;
    const int stride = gridDim.x * blockDim.x;

    float acc = 0.0f;

    #pragma unroll 2
    for (int p = tid; p < N_QUADS; p += stride) {
        int4 s = __ldg(&src4[p]);
        int4 d = __ldg(&dst4[p]);

        float2 ps0 = __ldg(&pos[s.x]);
        float2 ps1 = __ldg(&pos[s.y]);
        float2 ps2 = __ldg(&pos[s.z]);
        float2 ps3 = __ldg(&pos[s.w]);
        float2 pd0 = __ldg(&pos[d.x]);
        float2 pd1 = __ldg(&pos[d.y]);
        float2 pd2 = __ldg(&pos[d.z]);
        float2 pd3 = __ldg(&pos[d.w]);

        float dx0 = pd0.x - ps0.x, dy0 = pd0.y - ps0.y;
        float dx1 = pd1.x - ps1.x, dy1 = pd1.y - ps1.y;
        float dx2 = pd2.x - ps2.x, dy2 = pd2.y - ps2.y;
        float dx3 = pd3.x - ps3.x, dy3 = pd3.y - ps3.y;

        float r0 = sqrtf(fmaf(dx0, dx0, dy0 * dy0));
        float r1 = sqrtf(fmaf(dx1, dx1, dy1 * dy1));
        float r2 = sqrtf(fmaf(dx2, dx2, dy2 * dy2));
        float r3 = sqrtf(fmaf(dx3, dx3, dy3 * dy3));

        acc += (__expf(-r0) + __expf(-r1)) + (__expf(-r2) + __expf(-r3));
    }

    // warp reduce
    #pragma unroll
    for (int off = 16; off > 0; off >>= 1)
        acc += __shfl_xor_sync(0xFFFFFFFFu, acc, off);

    // block reduce via smem
    __shared__ float warp_sums[MAIN_THREADS / 32];
    __shared__ bool  is_last;
    const int lane = threadIdx.x & 31;
    const int wid  = threadIdx.x >> 5;
    if (lane == 0) warp_sums[wid] = acc;
    __syncthreads();

    if (wid == 0) {
        float b = (lane < (MAIN_THREADS / 32)) ? warp_sums[lane] : 0.0f;
        #pragma unroll
        for (int off = 16; off > 0; off >>= 1)
            b += __shfl_xor_sync(0xFFFFFFFFu, b, off);
        if (lane == 0) {
            g_partials[blockIdx.x] = b;
            __threadfence();
            unsigned int t = atomicAdd(&g_count, 1u);
            is_last = (t == (unsigned)gridDim.x - 1u);
        }
    }
    __syncthreads();

    // Last block to finish sums all partials (deterministic order) and writes out.
    if (is_last) {
        float s = 0.0f;
        for (int i = threadIdx.x; i < MAIN_BLOCKS; i += MAIN_THREADS) {
            float v;
            asm volatile("ld.global.cg.f32 %0, [%1];" : "=f"(v) : "l"(&g_partials[i]));
            s += v;
        }
        #pragma unroll
        for (int off = 16; off > 0; off >>= 1)
            s += __shfl_xor_sync(0xFFFFFFFFu, s, off);
        if (lane == 0) warp_sums[wid] = s;
        __syncthreads();
        if (wid == 0) {
            float b = (lane < (MAIN_THREADS / 32)) ? warp_sums[lane] : 0.0f;
            #pragma unroll
            for (int off = 16; off > 0; off >>= 1)
                b += __shfl_xor_sync(0xFFFFFFFFu, b, off);
            if (lane == 0) {
                out[0]  = b * (1.0f / (float)NUM_GRAPHS);
                g_count = 0;   // reset for next graph replay
            }
        }
    }
}

extern "C" void kernel_launch(void* const* d_in, const int* in_sizes, int n_in,
                              void* d_out, int out_size)
{
    // metadata order: node_pos f32 [131072,2], full_edge_index int32 [2, 8388608],
    //                 batch_idx int32 [131072] (unused: mean over full segment_sum
    //                 == total_sum / NUM_GRAPHS since all indices are in range)
    const float2* pos  = (const float2*)d_in[0];
    const int*    eidx = (const int*)d_in[1];
    float*        out  = (float*)d_out;

    const int4* src4 = (const int4*)(eidx);            // row 0
    const int4* dst4 = (const int4*)(eidx + N_EDGES);  // row 1

    occl_kernel<<<MAIN_BLOCKS, MAIN_THREADS>>>(pos, src4, dst4, out);
}